// round 7
// baseline (speedup 1.0000x reference)
#include <cuda_runtime.h>
#include <cstdint>

#define B_    32
#define HW_   128
#define NPIX  16384
#define NIMG  2048

// 128MB scratch: f2 (tf32-rounded) transposed [b,c,w,h], then (f6+f2) in-place
__device__ float g_scratch[(size_t)B_ * 64 * NPIX];
// pre-converted tf32 weights in per-thread fragment order
__device__ float g_wtf[8192];

__device__ __forceinline__ uint32_t f2tf(float x) {
    uint32_t r; asm("cvt.rna.tf32.f32 %0, %1;" : "=r"(r) : "f"(x)); return r;
}
__device__ __forceinline__ float softth(float x, float t) {
    float tt = fmaxf(t, 0.f);
    return copysignf(fmaxf(fabsf(x) - tt, 0.f), x);
}
__device__ __forceinline__ void mma_tf32(float* d, uint32_t a0, uint32_t a1, uint32_t a2, uint32_t a3,
                                         uint32_t b0, uint32_t b1) {
    asm volatile(
        "mma.sync.aligned.m16n8k8.row.col.f32.tf32.tf32.f32 "
        "{%0,%1,%2,%3}, {%4,%5,%6,%7}, {%8,%9}, {%0,%1,%2,%3};\n"
        : "+f"(d[0]), "+f"(d[1]), "+f"(d[2]), "+f"(d[3])
        : "r"(a0), "r"(a1), "r"(a2), "r"(a3), "r"(b0), "r"(b1));
}

// ---------------------------------------------------------------------------
// prep: conv_w -> tf32, fragment-ordered for podmix mainloop
// ---------------------------------------------------------------------------
__global__ void prep_kernel(const float* __restrict__ W)
{
    int t = blockIdx.x * 256 + threadIdx.x;
    if (t >= 1024) return;
    int tig = t & 3, gid = (t >> 2) & 7, mq = (t >> 5) & 3, kb = t >> 7;
    int k0 = kb * 8 + tig;
    int r0 = mq * 16 + gid;
    float* o = g_wtf + t * 8;
    o[0] = __uint_as_float(f2tf(__ldg(W + r0 * 64 + k0)));
    o[1] = __uint_as_float(f2tf(__ldg(W + (r0 + 8) * 64 + k0)));
    o[2] = __uint_as_float(f2tf(__ldg(W + r0 * 64 + k0 + 4)));
    o[3] = __uint_as_float(f2tf(__ldg(W + (r0 + 8) * 64 + k0 + 4)));
    int r1 = r0 + 64;
    o[4] = __uint_as_float(f2tf(__ldg(W + r1 * 64 + k0)));
    o[5] = __uint_as_float(f2tf(__ldg(W + (r1 + 8) * 64 + k0)));
    o[6] = __uint_as_float(f2tf(__ldg(W + r1 * 64 + k0 + 4)));
    o[7] = __uint_as_float(f2tf(__ldg(W + (r1 + 8) * 64 + k0 + 4)));
}

// ---------------------------------------------------------------------------
// Pass 1 / Pass 3: 2D FWHT of 128x128 image, output TRANSPOSED, scaled.
// 32 elems/thread; stage 64 folded at load, 1..8 & 32 in regs, 16 via shfl.
// Thread (rr = tid>>1, hq = tid&1). Per axis-vector, threads hq=0/1 own the
// interleaved 16-blocks [hq*16,+16) and [32+hq*16,+16) of the folded 64-space.
// smem rotation layout word(c,r) = c*128 + ((r+c)&127): conflict-free for
// both phase-W stores and phase-H loads.
// ---------------------------------------------------------------------------
__global__ void __launch_bounds__(256, 4)
fwht2d_kernel(const float* __restrict__ in, float* __restrict__ out,
              float scale, int do_round)
{
    extern __shared__ float s[];
    const int img = blockIdx.x;
    const int tid = threadIdx.x;
    const int hq  = tid & 1;
    const int rr  = tid >> 1;              // row (phase W) / column (phase H)
    const float* gin  = in  + (size_t)img * NPIX;
    float*       gout = out + (size_t)img * NPIX;

    // ---- phase W: transform along last axis, direct from gmem ----
    #pragma unroll
    for (int half = 0; half < 2; half++) {
        float u[32];
        #pragma unroll
        for (int blk = 0; blk < 2; blk++) {
            int base = blk * 32 + hq * 16;
            #pragma unroll
            for (int q = 0; q < 4; q++) {
                float4 a = __ldg((const float4*)(gin + rr * 128 + base + q * 4));
                float4 b = __ldg((const float4*)(gin + rr * 128 + base + 64 + q * 4));
                int m = blk * 16 + q * 4;
                if (half == 0) {
                    u[m] = a.x + b.x; u[m+1] = a.y + b.y; u[m+2] = a.z + b.z; u[m+3] = a.w + b.w;
                } else {
                    u[m] = a.x - b.x; u[m+1] = a.y - b.y; u[m+2] = a.z - b.z; u[m+3] = a.w - b.w;
                }
            }
        }
        // stages 1,2,4,8 (within 16-blocks)
        #pragma unroll
        for (int st = 1; st < 16; st <<= 1)
            #pragma unroll
            for (int m = 0; m < 32; m++)
                if ((m & st) == 0) {
                    float a = u[m], b = u[m + st];
                    u[m] = a + b;  u[m + st] = a - b;
                }
        // stage 16: exchange with lane^1
        #pragma unroll
        for (int m = 0; m < 32; m++) {
            float recv = __shfl_xor_sync(0xffffffffu, u[m], 1);
            u[m] = hq ? (recv - u[m]) : (u[m] + recv);
        }
        // stage 32 (pairs m, m+16)
        #pragma unroll
        for (int m = 0; m < 16; m++) {
            float a = u[m], b = u[m + 16];
            u[m] = a + b;  u[m + 16] = a - b;
        }
        // store to smem rotation layout at column index c' = result position
        #pragma unroll
        for (int m = 0; m < 32; m++) {
            int cp = half * 64 + (m >> 4) * 32 + hq * 16 + (m & 15);
            s[cp * 128 + ((rr + cp) & 127)] = u[m];
        }
    }
    __syncthreads();

    // ---- phase H: transform along first axis (rows of transposed smem) ----
    #pragma unroll
    for (int half = 0; half < 2; half++) {
        float u[32];
        #pragma unroll
        for (int m = 0; m < 32; m++) {
            int r = (m >> 4) * 32 + hq * 16 + (m & 15);
            float a = s[rr * 128 + ((r + rr) & 127)];
            float b = s[rr * 128 + ((r + 64 + rr) & 127)];
            u[m] = half ? (a - b) : (a + b);
        }
        #pragma unroll
        for (int st = 1; st < 16; st <<= 1)
            #pragma unroll
            for (int m = 0; m < 32; m++)
                if ((m & st) == 0) {
                    float a = u[m], b = u[m + st];
                    u[m] = a + b;  u[m + st] = a - b;
                }
        #pragma unroll
        for (int m = 0; m < 32; m++) {
            float recv = __shfl_xor_sync(0xffffffffu, u[m], 1);
            u[m] = hq ? (recv - u[m]) : (u[m] + recv);
        }
        #pragma unroll
        for (int m = 0; m < 16; m++) {
            float a = u[m], b = u[m + 16];
            u[m] = a + b;  u[m + 16] = a - b;
        }
        // direct gmem store: contiguous 16-float blocks per (blk)
        #pragma unroll
        for (int blk = 0; blk < 2; blk++) {
            int r0 = half * 64 + blk * 32 + hq * 16;
            #pragma unroll
            for (int q = 0; q < 4; q++) {
                int m = blk * 16 + q * 4;
                float4 o;
                if (do_round) {
                    o = make_float4(__uint_as_float(f2tf(u[m])),   __uint_as_float(f2tf(u[m+1])),
                                    __uint_as_float(f2tf(u[m+2])), __uint_as_float(f2tf(u[m+3])));
                } else {
                    o = make_float4(u[m]*scale, u[m+1]*scale, u[m+2]*scale, u[m+3]*scale);
                }
                *(float4*)(gout + rr * 128 + r0 + q * 4) = o;
            }
        }
    }
}

// ---------------------------------------------------------------------------
// Pass 2: mma.sync tf32 per (b,w) tile, 512 threads (16 warps).
// Warp tile: pod-paired m16 x n32 (8 MMAs, acc 32 regs). A from L1-hot g_wtf.
// ---------------------------------------------------------------------------
__global__ void __launch_bounds__(512, 2)
podmix_kernel(float* __restrict__ f2, const float* __restrict__ v,
              const float* __restrict__ T)
{
    __shared__ float sm[9216];
    float*    Bs  = sm;               // [64 c][136 h] tf32 bits of f2 tile
    uint32_t* Bsu = (uint32_t*)sm;
    float*    vs0 = sm + 8704;
    float*    Ts0 = vs0 + 128;
    float*    vs1 = Ts0 + 128;
    float*    Ts1 = vs1 + 128;

    const int b    = blockIdx.x >> 7;
    const int w    = blockIdx.x & 127;
    const int tid  = threadIdx.x;
    const int wid  = tid >> 5;
    const int lane = tid & 31;
    const int gid  = lane >> 2;   // 0..7
    const int tig  = lane & 3;    // 0..3
    const int mq   = wid & 3;     // o-quarter (16 rows)
    const int nq   = wid >> 2;    // h quarter (32 cols)
    const int n0   = nq * 32;

    float* gtile = f2 + (((size_t)b * 64) * 128 + w) * 128;   // + c*NPIX + h

    // stage f2 tile (already tf32 bits) -> Bs, pure copy
    #pragma unroll
    for (int k = 0; k < 4; k++) {
        int i4 = k * 512 + tid;          // 2048 float4
        int c  = i4 >> 5;
        int h4 = i4 & 31;
        float4 t = __ldg((const float4*)(gtile + (size_t)c * NPIX) + h4);
        *(float4*)&Bs[c * 136 + h4 * 4] = t;
    }
    // v/T columns for this w
    {
        int g = tid >> 7;     // 0..3
        int h = tid & 127;
        if      (g == 0) vs0[h] = __ldg(v + h * 128 + w);
        else if (g == 1) Ts0[h] = __ldg(T + h * 128 + w);
        else if (g == 2) vs1[h] = __ldg(v + NPIX + h * 128 + w);
        else             Ts1[h] = __ldg(T + NPIX + h * 128 + w);
    }
    __syncthreads();

    float acc[8][4];
    #pragma unroll
    for (int i = 0; i < 8; i++) {
        acc[i][0] = 0.f; acc[i][1] = 0.f; acc[i][2] = 0.f; acc[i][3] = 0.f;
    }

    const float4* Aw = (const float4*)g_wtf;

    #pragma unroll
    for (int kb = 0; kb < 8; kb++) {
        int ai = (((kb * 4 + mq) * 8 + gid) * 4 + tig) * 2;
        float4 lo = __ldg(Aw + ai);
        float4 hi = __ldg(Aw + ai + 1);
        uint32_t a0 = __float_as_uint(lo.x), a1 = __float_as_uint(lo.y);
        uint32_t a2 = __float_as_uint(lo.z), a3 = __float_as_uint(lo.w);
        uint32_t a4 = __float_as_uint(hi.x), a5 = __float_as_uint(hi.y);
        uint32_t a6 = __float_as_uint(hi.z), a7 = __float_as_uint(hi.w);
        int r0 = (kb * 8 + tig) * 136 + n0 + gid;
        int r1 = r0 + 4 * 136;
        #pragma unroll
        for (int nb = 0; nb < 4; nb++) {
            uint32_t b0 = Bsu[r0 + nb * 8];
            uint32_t b1 = Bsu[r1 + nb * 8];
            mma_tf32(acc[nb],     a0, a1, a2, a3, b0, b1);   // pod 0
            mma_tf32(acc[4 + nb], a4, a5, a6, a7, b0, b1);   // pod 1
        }
    }
    __syncthreads();   // all GEMM reads of Bs done

    // epilogue: combine pods in registers, add f2, write back into Bs
    {
        const int o = mq * 16 + gid;
        #pragma unroll
        for (int nb = 0; nb < 4; nb++) {
            int h = n0 + nb * 8 + 2 * tig;
            float v0h = vs0[h], v0h1 = vs0[h+1], t0h = Ts0[h], t0h1 = Ts0[h+1];
            float v1h = vs1[h], v1h1 = vs1[h+1], t1h = Ts1[h], t1h1 = Ts1[h+1];
            float2 f0 = *(const float2*)&Bs[o * 136 + h];
            float2 f1 = *(const float2*)&Bs[(o + 8) * 136 + h];
            float2 r0 = make_float2(
                softth(v0h  * acc[nb][0], t0h)  + softth(v1h  * acc[4+nb][0], t1h)  + f0.x,
                softth(v0h1 * acc[nb][1], t0h1) + softth(v1h1 * acc[4+nb][1], t1h1) + f0.y);
            float2 r1 = make_float2(
                softth(v0h  * acc[nb][2], t0h)  + softth(v1h  * acc[4+nb][2], t1h)  + f1.x,
                softth(v0h1 * acc[nb][3], t0h1) + softth(v1h1 * acc[4+nb][3], t1h1) + f1.y);
            *(float2*)&Bs[o * 136 + h]       = r0;
            *(float2*)&Bs[(o + 8) * 136 + h] = r1;
        }
    }
    __syncthreads();

    // coalesced store back in place
    #pragma unroll
    for (int k = 0; k < 4; k++) {
        int i4 = k * 512 + tid;
        int c  = i4 >> 5;
        int h4 = i4 & 31;
        float4 t = *(const float4*)&Bs[c * 136 + h4 * 4];
        *((float4*)(gtile + (size_t)c * NPIX) + h4) = t;
    }
}

extern "C" void kernel_launch(void* const* d_in, const int* in_sizes, int n_in,
                              void* d_out, int out_size)
{
    (void)in_sizes; (void)n_in; (void)out_size;
    const float* x = (const float*)d_in[0];
    const float* v = (const float*)d_in[1];
    const float* T = (const float*)d_in[2];
    const float* W = (const float*)d_in[3];
    float* out = (float*)d_out;

    float* scratch = nullptr;
    cudaGetSymbolAddress((void**)&scratch, g_scratch);

    const int smem1 = 128 * 128 * 4;   // 65536 B
    cudaFuncSetAttribute(fwht2d_kernel, cudaFuncAttributeMaxDynamicSharedMemorySize, smem1);

    prep_kernel<<<4, 256>>>(W);
    fwht2d_kernel<<<NIMG, 256, smem1>>>(x, scratch, 1.0f, 1);
    podmix_kernel<<<B_ * 128, 512>>>(scratch, v, T);
    fwht2d_kernel<<<NIMG, 256, smem1>>>(scratch, out, 1.0f / 16384.0f, 0);
}

// round 8
// speedup vs baseline: 1.1898x; 1.1898x over previous
#include <cuda_runtime.h>
#include <cuda_fp16.h>
#include <cstdint>

#define B_    32
#define HW_   128
#define NPIX  16384
#define NIMG  2048

// 64MB fp16 scratch: f2 transposed [b,c,w,h], then (f6+f2) in-place
__device__ __half g_scratch[(size_t)B_ * 64 * NPIX];
// pre-converted tf32 weights in per-thread fragment order
__device__ float g_wtf[8192];

// XOR-swizzled smem layout for fwht, stride 128 words (no pad)
__device__ __forceinline__ int sidx(int r, int h) {
    return r * 128 + ((((h >> 2) ^ r) & 31) << 2) + (h & 3);
}
__device__ __forceinline__ int sidx4(int r, int h4) {
    return r * 128 + (((h4 ^ r) & 31) << 2);
}

__device__ __forceinline__ uint32_t f2tf(float x) {
    uint32_t r; asm("cvt.rna.tf32.f32 %0, %1;" : "=r"(r) : "f"(x)); return r;
}
__device__ __forceinline__ float softth(float x, float t) {
    float tt = fmaxf(t, 0.f);
    return copysignf(fmaxf(fabsf(x) - tt, 0.f), x);
}
__device__ __forceinline__ void mma_tf32(float* d, uint32_t a0, uint32_t a1, uint32_t a2, uint32_t a3,
                                         uint32_t b0, uint32_t b1) {
    asm volatile(
        "mma.sync.aligned.m16n8k8.row.col.f32.tf32.tf32.f32 "
        "{%0,%1,%2,%3}, {%4,%5,%6,%7}, {%8,%9}, {%0,%1,%2,%3};\n"
        : "+f"(d[0]), "+f"(d[1]), "+f"(d[2]), "+f"(d[3])
        : "r"(a0), "r"(a1), "r"(a2), "r"(a3), "r"(b0), "r"(b1));
}

// ---------------------------------------------------------------------------
// prep: conv_w -> tf32, fragment-ordered for podmix mainloop
// ---------------------------------------------------------------------------
__global__ void prep_kernel(const float* __restrict__ W)
{
    int t = blockIdx.x * 256 + threadIdx.x;
    if (t >= 1024) return;
    int tig = t & 3, gid = (t >> 2) & 7, mq = (t >> 5) & 3, kb = t >> 7;
    int k0 = kb * 8 + tig;
    int r0 = mq * 16 + gid;
    float* o = g_wtf + t * 8;
    o[0] = __uint_as_float(f2tf(__ldg(W + r0 * 64 + k0)));
    o[1] = __uint_as_float(f2tf(__ldg(W + (r0 + 8) * 64 + k0)));
    o[2] = __uint_as_float(f2tf(__ldg(W + r0 * 64 + k0 + 4)));
    o[3] = __uint_as_float(f2tf(__ldg(W + (r0 + 8) * 64 + k0 + 4)));
    int r1 = r0 + 64;
    o[4] = __uint_as_float(f2tf(__ldg(W + r1 * 64 + k0)));
    o[5] = __uint_as_float(f2tf(__ldg(W + (r1 + 8) * 64 + k0)));
    o[6] = __uint_as_float(f2tf(__ldg(W + r1 * 64 + k0 + 4)));
    o[7] = __uint_as_float(f2tf(__ldg(W + (r1 + 8) * 64 + k0 + 4)));
}

// ---------------------------------------------------------------------------
// Pass 1 / Pass 3: 2D FWHT of 128x128 image, output TRANSPOSED, scaled.
// IN_F16 / OUT_F16 select scratch dtype on the corresponding side.
// (Proven R5 structure; only I/O conversion differs.)
// ---------------------------------------------------------------------------
template<bool IN_F16, bool OUT_F16>
__global__ void __launch_bounds__(256, 2)
fwht2d_kernel(const void* __restrict__ in_, void* __restrict__ out_, float scale)
{
    extern __shared__ float s[];
    const int img = blockIdx.x;
    const int tid = threadIdx.x;

    // stage in: gmem -> swizzled smem (float4 chunks)
    if (IN_F16) {
        const __half* gin = (const __half*)in_ + (size_t)img * NPIX;
        #pragma unroll
        for (int k = 0; k < 16; k++) {
            int gi = k * 256 + tid;            // 4-element chunk index
            int r  = gi >> 5;
            int c4 = gi & 31;
            uint2 p = __ldg((const uint2*)gin + gi);
            float2 f0 = __half22float2(*(__half2*)&p.x);
            float2 f1 = __half22float2(*(__half2*)&p.y);
            *(float4*)&s[sidx4(r, c4)] = make_float4(f0.x, f0.y, f1.x, f1.y);
        }
    } else {
        const float* gin = (const float*)in_ + (size_t)img * NPIX;
        #pragma unroll
        for (int k = 0; k < 16; k++) {
            int gi = k * 256 + tid;
            int r  = gi >> 5;
            int c4 = gi & 31;
            float4 v4 = __ldg((const float4*)gin + gi);
            *(float4*)&s[sidx4(r, c4)] = v4;
        }
    }
    __syncthreads();

    float reg[64];

    // phase W: transform along last axis. thread = (row r, half)
    {
        int r = tid >> 1, half = tid & 1;
        #pragma unroll
        for (int j4 = 0; j4 < 16; j4++) {
            float4 a = *(const float4*)&s[sidx4(r, j4)];
            float4 b = *(const float4*)&s[sidx4(r, j4 + 16)];
            if (half) {
                reg[4*j4+0] = a.x - b.x; reg[4*j4+1] = a.y - b.y;
                reg[4*j4+2] = a.z - b.z; reg[4*j4+3] = a.w - b.w;
            } else {
                reg[4*j4+0] = a.x + b.x; reg[4*j4+1] = a.y + b.y;
                reg[4*j4+2] = a.z + b.z; reg[4*j4+3] = a.w + b.w;
            }
        }
        #pragma unroll
        for (int st = 1; st < 64; st <<= 1)
            #pragma unroll
            for (int i = 0; i < 64; i++)
                if ((i & st) == 0) {
                    float a = reg[i], b = reg[i + st];
                    reg[i] = a + b;  reg[i + st] = a - b;
                }
        __syncthreads();
        #pragma unroll
        for (int j4 = 0; j4 < 16; j4++)
            *(float4*)&s[sidx4(r, half * 16 + j4)] =
                make_float4(reg[4*j4], reg[4*j4+1], reg[4*j4+2], reg[4*j4+3]);
    }
    __syncthreads();

    // phase H: transform along first axis (writes transposed)
    {
        int w = tid & 127, hh = tid >> 7;
        #pragma unroll
        for (int j = 0; j < 64; j++) {
            float a = s[sidx(j, w)];
            float b = s[sidx(j + 64, w)];
            reg[j] = hh ? (a - b) : (a + b);
        }
        #pragma unroll
        for (int st = 1; st < 64; st <<= 1)
            #pragma unroll
            for (int i = 0; i < 64; i++)
                if ((i & st) == 0) {
                    float a = reg[i], b = reg[i + st];
                    reg[i] = a + b;  reg[i + st] = a - b;
                }
        __syncthreads();
        #pragma unroll
        for (int j4 = 0; j4 < 16; j4++)
            *(float4*)&s[sidx4(w, hh * 16 + j4)] =
                make_float4(reg[4*j4], reg[4*j4+1], reg[4*j4+2], reg[4*j4+3]);
    }
    __syncthreads();

    // stage out
    if (OUT_F16) {
        __half* gout = (__half*)out_ + (size_t)img * NPIX;
        #pragma unroll
        for (int k = 0; k < 16; k++) {
            int gi = k * 256 + tid;
            int r  = gi >> 5;
            int c4 = gi & 31;
            float4 t = *(const float4*)&s[sidx4(r, c4)];
            __half2 h0 = __float22half2_rn(make_float2(t.x, t.y));
            __half2 h1 = __float22half2_rn(make_float2(t.z, t.w));
            uint2 p = make_uint2(*(uint32_t*)&h0, *(uint32_t*)&h1);
            ((uint2*)gout)[gi] = p;
        }
    } else {
        float* gout = (float*)out_ + (size_t)img * NPIX;
        #pragma unroll
        for (int k = 0; k < 16; k++) {
            int gi = k * 256 + tid;
            int r  = gi >> 5;
            int c4 = gi & 31;
            float4 t = *(const float4*)&s[sidx4(r, c4)];
            ((float4*)gout)[gi] = make_float4(t.x*scale, t.y*scale, t.z*scale, t.w*scale);
        }
    }
}

// ---------------------------------------------------------------------------
// Pass 2: mma.sync tf32 per (b,w) tile (proven R5 structure), fp16 gmem I/O.
// fp16->f32 conversion is exact and yields valid tf32 bit patterns.
// ---------------------------------------------------------------------------
__global__ void __launch_bounds__(256, 2)
podmix_kernel(__half* __restrict__ f2, const float* __restrict__ v,
              const float* __restrict__ T)
{
    __shared__ float sm[9216];
    float*    Bs  = sm;               // [64 c][136 h] f32/tf32 bits of f2 tile
    uint32_t* Bsu = (uint32_t*)sm;
    float*    vs0 = sm + 8704;
    float*    Ts0 = vs0 + 128;
    float*    vs1 = Ts0 + 128;
    float*    Ts1 = vs1 + 128;

    const int b    = blockIdx.x >> 7;
    const int w    = blockIdx.x & 127;
    const int tid  = threadIdx.x;
    const int wid  = tid >> 5;
    const int lane = tid & 31;
    const int gid  = lane >> 2;   // 0..7
    const int tig  = lane & 3;    // 0..3
    const int mq   = wid & 3;     // o-quarter (16 rows)
    const int nh   = wid >> 2;    // h half

    __half* gtile = f2 + (((size_t)b * 64) * 128 + w) * 128;   // + c*NPIX + h

    // stage fp16 f2 tile -> Bs (f32, tf32-clean)
    #pragma unroll
    for (int k = 0; k < 8; k++) {
        int i4 = k * 256 + tid;          // 2048 4-elem chunks
        int c  = i4 >> 5;
        int h4 = i4 & 31;
        uint2 p = __ldg((const uint2*)(gtile + (size_t)c * NPIX) + h4);
        float2 f0 = __half22float2(*(__half2*)&p.x);
        float2 f1 = __half22float2(*(__half2*)&p.y);
        *(float4*)&Bs[c * 136 + h4 * 4] = make_float4(f0.x, f0.y, f1.x, f1.y);
    }
    // v/T columns for this w
    if (tid < 128) {
        vs0[tid] = __ldg(v + tid * 128 + w);
        Ts0[tid] = __ldg(T + tid * 128 + w);
    } else {
        int h = tid - 128;
        vs1[h] = __ldg(v + NPIX + h * 128 + w);
        Ts1[h] = __ldg(T + NPIX + h * 128 + w);
    }
    __syncthreads();

    float acc[16][4];
    #pragma unroll
    for (int i = 0; i < 16; i++) {
        acc[i][0] = 0.f; acc[i][1] = 0.f; acc[i][2] = 0.f; acc[i][3] = 0.f;
    }

    const float4* Aw = (const float4*)g_wtf;

    #pragma unroll
    for (int kb = 0; kb < 8; kb++) {
        int ai = (((kb * 4 + mq) * 8 + gid) * 4 + tig) * 2;
        float4 lo = __ldg(Aw + ai);
        float4 hi = __ldg(Aw + ai + 1);
        uint32_t a0 = __float_as_uint(lo.x), a1 = __float_as_uint(lo.y);
        uint32_t a2 = __float_as_uint(lo.z), a3 = __float_as_uint(lo.w);
        uint32_t a4 = __float_as_uint(hi.x), a5 = __float_as_uint(hi.y);
        uint32_t a6 = __float_as_uint(hi.z), a7 = __float_as_uint(hi.w);
        int r0 = (kb * 8 + tig) * 136 + nh * 64 + gid;
        int r1 = r0 + 4 * 136;
        #pragma unroll
        for (int nb = 0; nb < 8; nb++) {
            uint32_t b0 = Bsu[r0 + nb * 8];
            uint32_t b1 = Bsu[r1 + nb * 8];
            mma_tf32(acc[nb],     a0, a1, a2, a3, b0, b1);   // pod 0
            mma_tf32(acc[8 + nb], a4, a5, a6, a7, b0, b1);   // pod 1
        }
    }
    __syncthreads();   // all GEMM reads of Bs done

    // epilogue: combine pods in registers, add f2, write back into Bs
    {
        const int o = mq * 16 + gid;
        #pragma unroll
        for (int nb = 0; nb < 8; nb++) {
            int h = nh * 64 + nb * 8 + 2 * tig;
            float v0h = vs0[h], v0h1 = vs0[h+1], t0h = Ts0[h], t0h1 = Ts0[h+1];
            float v1h = vs1[h], v1h1 = vs1[h+1], t1h = Ts1[h], t1h1 = Ts1[h+1];
            float2 f0 = *(const float2*)&Bs[o * 136 + h];
            float2 f1 = *(const float2*)&Bs[(o + 8) * 136 + h];
            float2 r0 = make_float2(
                softth(v0h  * acc[nb][0], t0h)  + softth(v1h  * acc[8+nb][0], t1h)  + f0.x,
                softth(v0h1 * acc[nb][1], t0h1) + softth(v1h1 * acc[8+nb][1], t1h1) + f0.y);
            float2 r1 = make_float2(
                softth(v0h  * acc[nb][2], t0h)  + softth(v1h  * acc[8+nb][2], t1h)  + f1.x,
                softth(v0h1 * acc[nb][3], t0h1) + softth(v1h1 * acc[8+nb][3], t1h1) + f1.y);
            *(float2*)&Bs[o * 136 + h]       = r0;
            *(float2*)&Bs[(o + 8) * 136 + h] = r1;
        }
    }
    __syncthreads();

    // coalesced fp16 store back in place
    #pragma unroll
    for (int k = 0; k < 8; k++) {
        int i4 = k * 256 + tid;
        int c  = i4 >> 5;
        int h4 = i4 & 31;
        float4 t = *(const float4*)&Bs[c * 136 + h4 * 4];
        __half2 h0 = __float22half2_rn(make_float2(t.x, t.y));
        __half2 h1 = __float22half2_rn(make_float2(t.z, t.w));
        uint2 p = make_uint2(*(uint32_t*)&h0, *(uint32_t*)&h1);
        *((uint2*)(gtile + (size_t)c * NPIX) + h4) = p;
    }
}

extern "C" void kernel_launch(void* const* d_in, const int* in_sizes, int n_in,
                              void* d_out, int out_size)
{
    (void)in_sizes; (void)n_in; (void)out_size;
    const float* x = (const float*)d_in[0];
    const float* v = (const float*)d_in[1];
    const float* T = (const float*)d_in[2];
    const float* W = (const float*)d_in[3];
    float* out = (float*)d_out;

    __half* scratch = nullptr;
    cudaGetSymbolAddress((void**)&scratch, g_scratch);

    const int smem1 = 128 * 128 * 4;   // 65536 B
    cudaFuncSetAttribute(fwht2d_kernel<false, true>,
                         cudaFuncAttributeMaxDynamicSharedMemorySize, smem1);
    cudaFuncSetAttribute(fwht2d_kernel<true, false>,
                         cudaFuncAttributeMaxDynamicSharedMemorySize, smem1);

    prep_kernel<<<4, 256>>>(W);
    fwht2d_kernel<false, true><<<NIMG, 256, smem1>>>(x, scratch, 1.0f);
    podmix_kernel<<<B_ * 128, 256>>>(scratch, v, T);
    fwht2d_kernel<true, false><<<NIMG, 256, smem1>>>(scratch, out, 1.0f / 16384.0f);
}

// round 9
// speedup vs baseline: 1.2771x; 1.0734x over previous
#include <cuda_runtime.h>
#include <cstdint>

#define B_    32
#define HW_   128
#define NPIX  16384
#define NIMG  2048

// 128MB scratch: f2 (tf32-rounded) transposed [b,c,w,h], then (f6+f2) in-place
__device__ float g_scratch[(size_t)B_ * 64 * NPIX];
// pre-converted tf32 weights in per-thread fragment order
__device__ float g_wtf[8192];

__device__ __forceinline__ uint32_t f2tf(float x) {
    uint32_t r; asm("cvt.rna.tf32.f32 %0, %1;" : "=r"(r) : "f"(x)); return r;
}
__device__ __forceinline__ float softth(float x, float t) {
    float tt = fmaxf(t, 0.f);
    return copysignf(fmaxf(fabsf(x) - tt, 0.f), x);
}
__device__ __forceinline__ void mma_tf32(float* d, uint32_t a0, uint32_t a1, uint32_t a2, uint32_t a3,
                                         uint32_t b0, uint32_t b1) {
    asm volatile(
        "mma.sync.aligned.m16n8k8.row.col.f32.tf32.tf32.f32 "
        "{%0,%1,%2,%3}, {%4,%5,%6,%7}, {%8,%9}, {%0,%1,%2,%3};\n"
        : "+f"(d[0]), "+f"(d[1]), "+f"(d[2]), "+f"(d[3])
        : "r"(a0), "r"(a1), "r"(a2), "r"(a3), "r"(b0), "r"(b1));
}

// 5-bit in-row permutation: injective, spreads h4 bits 3,4 into bank bits
__device__ __forceinline__ int inner5(int h4) {
    return h4 ^ ((h4 & 8) >> 1) ^ ((h4 & 16) >> 3);
}
// swizzled float4-granular address: row r (0..127), 16B chunk h4 (0..31)
__device__ __forceinline__ int swz4(int r, int h4) {
    return r * 128 + (((inner5(h4) ^ (r & 31)) & 31) << 2);
}
__device__ __forceinline__ int swz(int r, int h) {
    return swz4(r, h >> 2) + (h & 3);
}

// ---------------------------------------------------------------------------
// prep: conv_w -> tf32, fragment-ordered for podmix mainloop
// ---------------------------------------------------------------------------
__global__ void prep_kernel(const float* __restrict__ W)
{
    int t = blockIdx.x * 256 + threadIdx.x;
    if (t >= 1024) return;
    int tig = t & 3, gid = (t >> 2) & 7, mq = (t >> 5) & 3, kb = t >> 7;
    int k0 = kb * 8 + tig;
    int r0 = mq * 16 + gid;
    float* o = g_wtf + t * 8;
    o[0] = __uint_as_float(f2tf(__ldg(W + r0 * 64 + k0)));
    o[1] = __uint_as_float(f2tf(__ldg(W + (r0 + 8) * 64 + k0)));
    o[2] = __uint_as_float(f2tf(__ldg(W + r0 * 64 + k0 + 4)));
    o[3] = __uint_as_float(f2tf(__ldg(W + (r0 + 8) * 64 + k0 + 4)));
    int r1 = r0 + 64;
    o[4] = __uint_as_float(f2tf(__ldg(W + r1 * 64 + k0)));
    o[5] = __uint_as_float(f2tf(__ldg(W + (r1 + 8) * 64 + k0)));
    o[6] = __uint_as_float(f2tf(__ldg(W + r1 * 64 + k0 + 4)));
    o[7] = __uint_as_float(f2tf(__ldg(W + (r1 + 8) * 64 + k0 + 4)));
}

// ---------------------------------------------------------------------------
// Pass 1 / Pass 3: 2D FWHT of 128x128 image, output TRANSPOSED, scaled.
// 512 threads, 32 floats/thread: thread (rc=(tid>>1)&127, sub=tid&1, hf=tid>>8)
// owns output positions hf*64 + sub*32 + [0,32) of vector rc.
// Stage order per axis: 64 (fold at load), 1..16 in regs, 32 via shfl.xor(1).
// ---------------------------------------------------------------------------
__global__ void __launch_bounds__(512, 2)
fwht2d_kernel(const float* __restrict__ in, float* __restrict__ out,
              float scale, int do_round)
{
    extern __shared__ float s[];
    const int tid = threadIdx.x;
    const int sub = tid & 1;
    const int rc  = (tid >> 1) & 127;
    const int hf  = tid >> 8;
    const float* gin  = in  + (size_t)blockIdx.x * NPIX;
    float*       gout = out + (size_t)blockIdx.x * NPIX;

    // stage in: coalesced gmem -> swizzled smem
    #pragma unroll
    for (int k = 0; k < 8; k++) {
        int gi = k * 512 + tid;            // float4 index, 4096 total
        int r  = gi >> 5;
        int c4 = gi & 31;
        float4 v4 = __ldg((const float4*)gin + gi);
        *(float4*)&s[swz4(r, c4)] = v4;
    }
    __syncthreads();

    float u[32];

    // ---- phase W: transform along last axis ----
    #pragma unroll
    for (int j4 = 0; j4 < 8; j4++) {
        float4 a = *(const float4*)&s[swz4(rc, sub * 8 + j4)];
        float4 b = *(const float4*)&s[swz4(rc, sub * 8 + j4 + 16)];
        if (hf) {
            u[4*j4]   = a.x - b.x; u[4*j4+1] = a.y - b.y;
            u[4*j4+2] = a.z - b.z; u[4*j4+3] = a.w - b.w;
        } else {
            u[4*j4]   = a.x + b.x; u[4*j4+1] = a.y + b.y;
            u[4*j4+2] = a.z + b.z; u[4*j4+3] = a.w + b.w;
        }
    }
    #pragma unroll
    for (int st = 1; st < 32; st <<= 1)
        #pragma unroll
        for (int j = 0; j < 32; j++)
            if ((j & st) == 0) {
                float a = u[j], b = u[j + st];
                u[j] = a + b;  u[j + st] = a - b;
            }
    #pragma unroll
    for (int j = 0; j < 32; j++) {
        float recv = __shfl_xor_sync(0xffffffffu, u[j], 1);
        u[j] = sub ? (recv - u[j]) : (u[j] + recv);
    }
    __syncthreads();   // all phase-W reads complete before overwrite
    #pragma unroll
    for (int j4 = 0; j4 < 8; j4++)
        *(float4*)&s[swz4(rc, hf * 16 + sub * 8 + j4)] =
            make_float4(u[4*j4], u[4*j4+1], u[4*j4+2], u[4*j4+3]);
    __syncthreads();

    // ---- phase H: transform along first axis (column rc) ----
    #pragma unroll
    for (int j = 0; j < 32; j++) {
        int p = sub * 32 + j;
        float a = s[swz(p, rc)];
        float b = s[swz(p + 64, rc)];
        u[j] = hf ? (a - b) : (a + b);
    }
    #pragma unroll
    for (int st = 1; st < 32; st <<= 1)
        #pragma unroll
        for (int j = 0; j < 32; j++)
            if ((j & st) == 0) {
                float a = u[j], b = u[j + st];
                u[j] = a + b;  u[j + st] = a - b;
            }
    #pragma unroll
    for (int j = 0; j < 32; j++) {
        float recv = __shfl_xor_sync(0xffffffffu, u[j], 1);
        u[j] = sub ? (recv - u[j]) : (u[j] + recv);
    }
    __syncthreads();   // all phase-H reads complete before overwrite
    // store TRANSPOSED: row rc of output
    #pragma unroll
    for (int j4 = 0; j4 < 8; j4++)
        *(float4*)&s[swz4(rc, hf * 16 + sub * 8 + j4)] =
            make_float4(u[4*j4], u[4*j4+1], u[4*j4+2], u[4*j4+3]);
    __syncthreads();

    // stage out: swizzled smem -> coalesced gmem
    if (do_round) {
        #pragma unroll
        for (int k = 0; k < 8; k++) {
            int gi = k * 512 + tid;
            int r  = gi >> 5;
            int c4 = gi & 31;
            float4 t = *(const float4*)&s[swz4(r, c4)];
            ((float4*)gout)[gi] = make_float4(
                __uint_as_float(f2tf(t.x)), __uint_as_float(f2tf(t.y)),
                __uint_as_float(f2tf(t.z)), __uint_as_float(f2tf(t.w)));
        }
    } else {
        #pragma unroll
        for (int k = 0; k < 8; k++) {
            int gi = k * 512 + tid;
            int r  = gi >> 5;
            int c4 = gi & 31;
            float4 t = *(const float4*)&s[swz4(r, c4)];
            ((float4*)gout)[gi] = make_float4(t.x*scale, t.y*scale, t.z*scale, t.w*scale);
        }
    }
}

// ---------------------------------------------------------------------------
// Pass 2: mma.sync tf32 per (b,w) tile (R5-proven structure, unchanged).
// ---------------------------------------------------------------------------
__global__ void __launch_bounds__(256, 2)
podmix_kernel(float* __restrict__ f2, const float* __restrict__ v,
              const float* __restrict__ T)
{
    __shared__ float sm[9216];
    float*    Bs  = sm;               // [64 c][136 h] tf32 bits of f2 tile
    uint32_t* Bsu = (uint32_t*)sm;
    float*    vs0 = sm + 8704;
    float*    Ts0 = vs0 + 128;
    float*    vs1 = Ts0 + 128;
    float*    Ts1 = vs1 + 128;

    const int b    = blockIdx.x >> 7;
    const int w    = blockIdx.x & 127;
    const int tid  = threadIdx.x;
    const int wid  = tid >> 5;
    const int lane = tid & 31;
    const int gid  = lane >> 2;   // 0..7
    const int tig  = lane & 3;    // 0..3
    const int mq   = wid & 3;     // o-quarter (16 rows)
    const int nh   = wid >> 2;    // h half

    float* gtile = f2 + (((size_t)b * 64) * 128 + w) * 128;   // + c*NPIX + h

    // stage f2 tile (already tf32 bits) -> Bs, pure copy
    #pragma unroll
    for (int k = 0; k < 8; k++) {
        int i4 = k * 256 + tid;          // 2048 float4
        int c  = i4 >> 5;
        int h4 = i4 & 31;
        float4 t = __ldg((const float4*)(gtile + (size_t)c * NPIX) + h4);
        *(float4*)&Bs[c * 136 + h4 * 4] = t;
    }
    // v/T columns for this w
    if (tid < 128) {
        vs0[tid] = __ldg(v + tid * 128 + w);
        Ts0[tid] = __ldg(T + tid * 128 + w);
    } else {
        int h = tid - 128;
        vs1[h] = __ldg(v + NPIX + h * 128 + w);
        Ts1[h] = __ldg(T + NPIX + h * 128 + w);
    }
    __syncthreads();

    float acc[16][4];
    #pragma unroll
    for (int i = 0; i < 16; i++) {
        acc[i][0] = 0.f; acc[i][1] = 0.f; acc[i][2] = 0.f; acc[i][3] = 0.f;
    }

    const float4* Aw = (const float4*)g_wtf;

    #pragma unroll
    for (int kb = 0; kb < 8; kb++) {
        int ai = (((kb * 4 + mq) * 8 + gid) * 4 + tig) * 2;
        float4 lo = __ldg(Aw + ai);
        float4 hi = __ldg(Aw + ai + 1);
        uint32_t a0 = __float_as_uint(lo.x), a1 = __float_as_uint(lo.y);
        uint32_t a2 = __float_as_uint(lo.z), a3 = __float_as_uint(lo.w);
        uint32_t a4 = __float_as_uint(hi.x), a5 = __float_as_uint(hi.y);
        uint32_t a6 = __float_as_uint(hi.z), a7 = __float_as_uint(hi.w);
        int r0 = (kb * 8 + tig) * 136 + nh * 64 + gid;
        int r1 = r0 + 4 * 136;
        #pragma unroll
        for (int nb = 0; nb < 8; nb++) {
            uint32_t b0 = Bsu[r0 + nb * 8];
            uint32_t b1 = Bsu[r1 + nb * 8];
            mma_tf32(acc[nb],     a0, a1, a2, a3, b0, b1);   // pod 0
            mma_tf32(acc[8 + nb], a4, a5, a6, a7, b0, b1);   // pod 1
        }
    }
    __syncthreads();   // all GEMM reads of Bs done

    // epilogue: combine pods in registers, add f2, write back into Bs
    {
        const int o = mq * 16 + gid;
        #pragma unroll
        for (int nb = 0; nb < 8; nb++) {
            int h = nh * 64 + nb * 8 + 2 * tig;
            float v0h = vs0[h], v0h1 = vs0[h+1], t0h = Ts0[h], t0h1 = Ts0[h+1];
            float v1h = vs1[h], v1h1 = vs1[h+1], t1h = Ts1[h], t1h1 = Ts1[h+1];
            float2 f0 = *(const float2*)&Bs[o * 136 + h];
            float2 f1 = *(const float2*)&Bs[(o + 8) * 136 + h];
            float2 r0 = make_float2(
                softth(v0h  * acc[nb][0], t0h)  + softth(v1h  * acc[8+nb][0], t1h)  + f0.x,
                softth(v0h1 * acc[nb][1], t0h1) + softth(v1h1 * acc[8+nb][1], t1h1) + f0.y);
            float2 r1 = make_float2(
                softth(v0h  * acc[nb][2], t0h)  + softth(v1h  * acc[8+nb][2], t1h)  + f1.x,
                softth(v0h1 * acc[nb][3], t0h1) + softth(v1h1 * acc[8+nb][3], t1h1) + f1.y);
            *(float2*)&Bs[o * 136 + h]       = r0;
            *(float2*)&Bs[(o + 8) * 136 + h] = r1;
        }
    }
    __syncthreads();

    // coalesced store back in place
    #pragma unroll
    for (int k = 0; k < 8; k++) {
        int i4 = k * 256 + tid;
        int c  = i4 >> 5;
        int h4 = i4 & 31;
        float4 t = *(const float4*)&Bs[c * 136 + h4 * 4];
        *((float4*)(gtile + (size_t)c * NPIX) + h4) = t;
    }
}

extern "C" void kernel_launch(void* const* d_in, const int* in_sizes, int n_in,
                              void* d_out, int out_size)
{
    (void)in_sizes; (void)n_in; (void)out_size;
    const float* x = (const float*)d_in[0];
    const float* v = (const float*)d_in[1];
    const float* T = (const float*)d_in[2];
    const float* W = (const float*)d_in[3];
    float* out = (float*)d_out;

    float* scratch = nullptr;
    cudaGetSymbolAddress((void**)&scratch, g_scratch);

    const int smem1 = 128 * 128 * 4;   // 65536 B
    cudaFuncSetAttribute(fwht2d_kernel, cudaFuncAttributeMaxDynamicSharedMemorySize, smem1);

    prep_kernel<<<4, 256>>>(W);
    fwht2d_kernel<<<NIMG, 512, smem1>>>(x, scratch, 1.0f, 1);
    podmix_kernel<<<B_ * 128, 256>>>(scratch, v, T);
    fwht2d_kernel<<<NIMG, 512, smem1>>>(scratch, out, 1.0f / 16384.0f, 0);
}

// round 10
// speedup vs baseline: 1.3877x; 1.0866x over previous
#include <cuda_runtime.h>
#include <cstdint>

#define B_    32
#define HW_   128
#define NPIX  16384
#define NIMG  2048

// 128MB scratch: f2 (tf32-rounded) transposed [b,c,w,h], then (f6+f2) in-place
__device__ float g_scratch[(size_t)B_ * 64 * NPIX];
// pre-converted tf32 weights in per-thread fragment order
__device__ float g_wtf[8192];

// XOR-swizzled smem layout for fwht, stride 128 words (no pad)
__device__ __forceinline__ int sidx(int r, int h) {
    return r * 128 + ((((h >> 2) ^ r) & 31) << 2) + (h & 3);
}
__device__ __forceinline__ int sidx4(int r, int h4) {
    return r * 128 + (((h4 ^ r) & 31) << 2);
}

__device__ __forceinline__ uint32_t f2tf(float x) {
    uint32_t r; asm("cvt.rna.tf32.f32 %0, %1;" : "=r"(r) : "f"(x)); return r;
}
__device__ __forceinline__ float softth(float x, float t) {
    float tt = fmaxf(t, 0.f);
    return copysignf(fmaxf(fabsf(x) - tt, 0.f), x);
}
__device__ __forceinline__ void mma_tf32(float* d, uint32_t a0, uint32_t a1, uint32_t a2, uint32_t a3,
                                         uint32_t b0, uint32_t b1) {
    asm volatile(
        "mma.sync.aligned.m16n8k8.row.col.f32.tf32.tf32.f32 "
        "{%0,%1,%2,%3}, {%4,%5,%6,%7}, {%8,%9}, {%0,%1,%2,%3};\n"
        : "+f"(d[0]), "+f"(d[1]), "+f"(d[2]), "+f"(d[3])
        : "r"(a0), "r"(a1), "r"(a2), "r"(a3), "r"(b0), "r"(b1));
}

// cp.async helpers
__device__ __forceinline__ void cpa16(uint32_t d, const void* s) {
    asm volatile("cp.async.cg.shared.global [%0], [%1], 16;" :: "r"(d), "l"(s));
}
__device__ __forceinline__ void cpa4(uint32_t d, const void* s) {
    asm volatile("cp.async.ca.shared.global [%0], [%1], 4;" :: "r"(d), "l"(s));
}

// ---------------------------------------------------------------------------
// prep: conv_w -> tf32, fragment-ordered for podmix mainloop
// ---------------------------------------------------------------------------
__global__ void prep_kernel(const float* __restrict__ W)
{
    int t = blockIdx.x * 256 + threadIdx.x;
    if (t >= 1024) return;
    int tig = t & 3, gid = (t >> 2) & 7, mq = (t >> 5) & 3, kb = t >> 7;
    int k0 = kb * 8 + tig;
    int r0 = mq * 16 + gid;
    float* o = g_wtf + t * 8;
    o[0] = __uint_as_float(f2tf(__ldg(W + r0 * 64 + k0)));
    o[1] = __uint_as_float(f2tf(__ldg(W + (r0 + 8) * 64 + k0)));
    o[2] = __uint_as_float(f2tf(__ldg(W + r0 * 64 + k0 + 4)));
    o[3] = __uint_as_float(f2tf(__ldg(W + (r0 + 8) * 64 + k0 + 4)));
    int r1 = r0 + 64;
    o[4] = __uint_as_float(f2tf(__ldg(W + r1 * 64 + k0)));
    o[5] = __uint_as_float(f2tf(__ldg(W + (r1 + 8) * 64 + k0)));
    o[6] = __uint_as_float(f2tf(__ldg(W + r1 * 64 + k0 + 4)));
    o[7] = __uint_as_float(f2tf(__ldg(W + (r1 + 8) * 64 + k0 + 4)));
}

// ---------------------------------------------------------------------------
// Pass 1 / Pass 3: 2D FWHT of 128x128 image, output TRANSPOSED, scaled.
// (Exact R5-proven structure: 256 threads, 64 floats/thread, XOR swizzle.)
// ---------------------------------------------------------------------------
__global__ void __launch_bounds__(256, 2)
fwht2d_kernel(const float* __restrict__ in, float* __restrict__ out,
              float scale, int do_round)
{
    extern __shared__ float s[];
    const int img = blockIdx.x;
    const int tid = threadIdx.x;
    const float* gin  = in  + (size_t)img * NPIX;
    float*       gout = out + (size_t)img * NPIX;

    #pragma unroll
    for (int k = 0; k < 16; k++) {
        int gi = k * 256 + tid;
        int r  = gi >> 5;
        int c4 = gi & 31;
        float4 v4 = __ldg((const float4*)gin + gi);
        *(float4*)&s[sidx4(r, c4)] = v4;
    }
    __syncthreads();

    float reg[64];

    // phase W
    {
        int r = tid >> 1, half = tid & 1;
        #pragma unroll
        for (int j4 = 0; j4 < 16; j4++) {
            float4 a = *(const float4*)&s[sidx4(r, j4)];
            float4 b = *(const float4*)&s[sidx4(r, j4 + 16)];
            if (half) {
                reg[4*j4+0] = a.x - b.x; reg[4*j4+1] = a.y - b.y;
                reg[4*j4+2] = a.z - b.z; reg[4*j4+3] = a.w - b.w;
            } else {
                reg[4*j4+0] = a.x + b.x; reg[4*j4+1] = a.y + b.y;
                reg[4*j4+2] = a.z + b.z; reg[4*j4+3] = a.w + b.w;
            }
        }
        #pragma unroll
        for (int st = 1; st < 64; st <<= 1)
            #pragma unroll
            for (int i = 0; i < 64; i++)
                if ((i & st) == 0) {
                    float a = reg[i], b = reg[i + st];
                    reg[i] = a + b;  reg[i + st] = a - b;
                }
        __syncthreads();
        #pragma unroll
        for (int j4 = 0; j4 < 16; j4++)
            *(float4*)&s[sidx4(r, half * 16 + j4)] =
                make_float4(reg[4*j4], reg[4*j4+1], reg[4*j4+2], reg[4*j4+3]);
    }
    __syncthreads();

    // phase H (writes transposed)
    {
        int w = tid & 127, hh = tid >> 7;
        #pragma unroll
        for (int j = 0; j < 64; j++) {
            float a = s[sidx(j, w)];
            float b = s[sidx(j + 64, w)];
            reg[j] = hh ? (a - b) : (a + b);
        }
        #pragma unroll
        for (int st = 1; st < 64; st <<= 1)
            #pragma unroll
            for (int i = 0; i < 64; i++)
                if ((i & st) == 0) {
                    float a = reg[i], b = reg[i + st];
                    reg[i] = a + b;  reg[i + st] = a - b;
                }
        __syncthreads();
        #pragma unroll
        for (int j4 = 0; j4 < 16; j4++)
            *(float4*)&s[sidx4(w, hh * 16 + j4)] =
                make_float4(reg[4*j4], reg[4*j4+1], reg[4*j4+2], reg[4*j4+3]);
    }
    __syncthreads();

    if (do_round) {
        #pragma unroll
        for (int k = 0; k < 16; k++) {
            int gi = k * 256 + tid;
            int r  = gi >> 5;
            int c4 = gi & 31;
            float4 t = *(const float4*)&s[sidx4(r, c4)];
            ((float4*)gout)[gi] = make_float4(
                __uint_as_float(f2tf(t.x)), __uint_as_float(f2tf(t.y)),
                __uint_as_float(f2tf(t.z)), __uint_as_float(f2tf(t.w)));
        }
    } else {
        #pragma unroll
        for (int k = 0; k < 16; k++) {
            int gi = k * 256 + tid;
            int r  = gi >> 5;
            int c4 = gi & 31;
            float4 t = *(const float4*)&s[sidx4(r, c4)];
            ((float4*)gout)[gi] = make_float4(t.x*scale, t.y*scale, t.z*scale, t.w*scale);
        }
    }
}

// ---------------------------------------------------------------------------
// Pass 2: mma.sync tf32; TWO adjacent tiles (w0, w0+1) per block, both
// prefetched up-front via cp.async so tile 1's DRAM fetch overlaps tile 0's
// compute + store. Compute/epilogue identical to proven R5.
// smem: Bs[2][64][136] + vt[2][512] = 73728 B
// ---------------------------------------------------------------------------
__global__ void __launch_bounds__(256, 2)
podmix_kernel(float* __restrict__ f2, const float* __restrict__ v,
              const float* __restrict__ T)
{
    extern __shared__ float sm[];
    const int tid  = threadIdx.x;
    const int wid  = tid >> 5;
    const int lane = tid & 31;
    const int gid  = lane >> 2;   // 0..7
    const int tig  = lane & 3;    // 0..3
    const int mq   = wid & 3;     // o-quarter (16 rows)
    const int nh   = wid >> 2;    // h half

    const int b  = blockIdx.x >> 6;
    const int w0 = (blockIdx.x & 63) * 2;

    // prefetch both tiles + their v/T columns
    #pragma unroll
    for (int tno = 0; tno < 2; tno++) {
        int w = w0 + tno;
        const float* gt = f2 + (((size_t)b * 64) * 128 + w) * 128;
        uint32_t bsd = (uint32_t)__cvta_generic_to_shared(sm + tno * 8704);
        #pragma unroll
        for (int k = 0; k < 8; k++) {
            int i4 = k * 256 + tid, c = i4 >> 5, h4 = i4 & 31;
            cpa16(bsd + (c * 136 + h4 * 4) * 4, gt + (size_t)c * NPIX + h4 * 4);
        }
        uint32_t vtd = (uint32_t)__cvta_generic_to_shared(sm + 17408 + tno * 512);
        if (tid < 128) {
            cpa4(vtd + tid * 4,       v + tid * 128 + w);
            cpa4(vtd + 512 + tid * 4, T + tid * 128 + w);
        } else {
            int h = tid - 128;
            cpa4(vtd + 1024 + h * 4, v + NPIX + h * 128 + w);
            cpa4(vtd + 1536 + h * 4, T + NPIX + h * 128 + w);
        }
        asm volatile("cp.async.commit_group;" ::: "memory");
    }

    const float4* Aw = (const float4*)g_wtf;

    #pragma unroll
    for (int tno = 0; tno < 2; tno++) {
        if (tno == 0)
            asm volatile("cp.async.wait_group 1;" ::: "memory");
        else
            asm volatile("cp.async.wait_group 0;" ::: "memory");
        __syncthreads();

        float*    Bs  = sm + tno * 8704;
        uint32_t* Bsu = (uint32_t*)Bs;
        const float* vs0 = sm + 17408 + tno * 512;
        const float* Ts0 = vs0 + 128;
        const float* vs1 = vs0 + 256;
        const float* Ts1 = vs0 + 384;
        float* gt = f2 + (((size_t)b * 64) * 128 + (w0 + tno)) * 128;

        float acc[16][4];
        #pragma unroll
        for (int i = 0; i < 16; i++) {
            acc[i][0] = 0.f; acc[i][1] = 0.f; acc[i][2] = 0.f; acc[i][3] = 0.f;
        }

        #pragma unroll
        for (int kb = 0; kb < 8; kb++) {
            int ai = (((kb * 4 + mq) * 8 + gid) * 4 + tig) * 2;
            float4 lo = __ldg(Aw + ai);
            float4 hi = __ldg(Aw + ai + 1);
            uint32_t a0 = __float_as_uint(lo.x), a1 = __float_as_uint(lo.y);
            uint32_t a2 = __float_as_uint(lo.z), a3 = __float_as_uint(lo.w);
            uint32_t a4 = __float_as_uint(hi.x), a5 = __float_as_uint(hi.y);
            uint32_t a6 = __float_as_uint(hi.z), a7 = __float_as_uint(hi.w);
            int r0 = (kb * 8 + tig) * 136 + nh * 64 + gid;
            int r1 = r0 + 4 * 136;
            #pragma unroll
            for (int nb = 0; nb < 8; nb++) {
                uint32_t b0 = Bsu[r0 + nb * 8];
                uint32_t b1 = Bsu[r1 + nb * 8];
                mma_tf32(acc[nb],     a0, a1, a2, a3, b0, b1);   // pod 0
                mma_tf32(acc[8 + nb], a4, a5, a6, a7, b0, b1);   // pod 1
            }
        }
        __syncthreads();   // all GEMM reads of Bs done

        // epilogue: combine pods in registers, add f2, write back into Bs
        {
            const int o = mq * 16 + gid;
            #pragma unroll
            for (int nb = 0; nb < 8; nb++) {
                int h = nh * 64 + nb * 8 + 2 * tig;
                float v0h = vs0[h], v0h1 = vs0[h+1], t0h = Ts0[h], t0h1 = Ts0[h+1];
                float v1h = vs1[h], v1h1 = vs1[h+1], t1h = Ts1[h], t1h1 = Ts1[h+1];
                float2 f0 = *(const float2*)&Bs[o * 136 + h];
                float2 f1 = *(const float2*)&Bs[(o + 8) * 136 + h];
                float2 r0 = make_float2(
                    softth(v0h  * acc[nb][0], t0h)  + softth(v1h  * acc[8+nb][0], t1h)  + f0.x,
                    softth(v0h1 * acc[nb][1], t0h1) + softth(v1h1 * acc[8+nb][1], t1h1) + f0.y);
                float2 r1 = make_float2(
                    softth(v0h  * acc[nb][2], t0h)  + softth(v1h  * acc[8+nb][2], t1h)  + f1.x,
                    softth(v0h1 * acc[nb][3], t0h1) + softth(v1h1 * acc[8+nb][3], t1h1) + f1.y);
                *(float2*)&Bs[o * 136 + h]       = r0;
                *(float2*)&Bs[(o + 8) * 136 + h] = r1;
            }
        }
        __syncthreads();

        // coalesced store back in place
        #pragma unroll
        for (int k = 0; k < 8; k++) {
            int i4 = k * 256 + tid;
            int c  = i4 >> 5;
            int h4 = i4 & 31;
            float4 t = *(const float4*)&Bs[c * 136 + h4 * 4];
            *((float4*)(gt + (size_t)c * NPIX) + h4) = t;
        }
    }
}

extern "C" void kernel_launch(void* const* d_in, const int* in_sizes, int n_in,
                              void* d_out, int out_size)
{
    (void)in_sizes; (void)n_in; (void)out_size;
    const float* x = (const float*)d_in[0];
    const float* v = (const float*)d_in[1];
    const float* T = (const float*)d_in[2];
    const float* W = (const float*)d_in[3];
    float* out = (float*)d_out;

    float* scratch = nullptr;
    cudaGetSymbolAddress((void**)&scratch, g_scratch);

    const int smem1 = 128 * 128 * 4;          // 65536 B
    const int smem2 = (17408 + 1024) * 4;     // 73728 B
    cudaFuncSetAttribute(fwht2d_kernel, cudaFuncAttributeMaxDynamicSharedMemorySize, smem1);
    cudaFuncSetAttribute(podmix_kernel, cudaFuncAttributeMaxDynamicSharedMemorySize, smem2);

    prep_kernel<<<4, 256>>>(W);
    fwht2d_kernel<<<NIMG, 256, smem1>>>(x, scratch, 1.0f, 1);
    podmix_kernel<<<B_ * 64, 256, smem2>>>(scratch, v, T);
    fwht2d_kernel<<<NIMG, 256, smem1>>>(scratch, out, 1.0f / 16384.0f, 0);
}

// round 11
// speedup vs baseline: 1.3910x; 1.0024x over previous
#include <cuda_runtime.h>
#include <cstdint>

#define B_    32
#define HW_   128
#define NPIX  16384
#define NIMG  2048

// 128MB scratch: f2 (tf32-rounded) transposed [b,c,w,h], then (f6+f2) in-place
__device__ float g_scratch[(size_t)B_ * 64 * NPIX];
// pre-converted tf32 weights in per-thread fragment order
__device__ float g_wtf[8192];

// XOR-swizzled smem layout for fwht, stride 128 words (no pad)
__device__ __forceinline__ int sidx(int r, int h) {
    return r * 128 + ((((h >> 2) ^ r) & 31) << 2) + (h & 3);
}
__device__ __forceinline__ int sidx4(int r, int h4) {
    return r * 128 + (((h4 ^ r) & 31) << 2);
}

__device__ __forceinline__ uint32_t f2tf(float x) {
    uint32_t r; asm("cvt.rna.tf32.f32 %0, %1;" : "=r"(r) : "f"(x)); return r;
}
__device__ __forceinline__ float softth(float x, float t) {
    float tt = fmaxf(t, 0.f);
    return copysignf(fmaxf(fabsf(x) - tt, 0.f), x);
}
__device__ __forceinline__ void mma_tf32(float* d, uint32_t a0, uint32_t a1, uint32_t a2, uint32_t a3,
                                         uint32_t b0, uint32_t b1) {
    asm volatile(
        "mma.sync.aligned.m16n8k8.row.col.f32.tf32.tf32.f32 "
        "{%0,%1,%2,%3}, {%4,%5,%6,%7}, {%8,%9}, {%0,%1,%2,%3};\n"
        : "+f"(d[0]), "+f"(d[1]), "+f"(d[2]), "+f"(d[3])
        : "r"(a0), "r"(a1), "r"(a2), "r"(a3), "r"(b0), "r"(b1));
}

// ---------------------------------------------------------------------------
// prep: conv_w -> tf32, fragment-ordered for podmix mainloop
// ---------------------------------------------------------------------------
__global__ void prep_kernel(const float* __restrict__ W)
{
    int t = blockIdx.x * 256 + threadIdx.x;
    if (t >= 1024) return;
    int tig = t & 3, gid = (t >> 2) & 7, mq = (t >> 5) & 3, kb = t >> 7;
    int k0 = kb * 8 + tig;
    int r0 = mq * 16 + gid;
    float* o = g_wtf + t * 8;
    o[0] = __uint_as_float(f2tf(__ldg(W + r0 * 64 + k0)));
    o[1] = __uint_as_float(f2tf(__ldg(W + (r0 + 8) * 64 + k0)));
    o[2] = __uint_as_float(f2tf(__ldg(W + r0 * 64 + k0 + 4)));
    o[3] = __uint_as_float(f2tf(__ldg(W + (r0 + 8) * 64 + k0 + 4)));
    int r1 = r0 + 64;
    o[4] = __uint_as_float(f2tf(__ldg(W + r1 * 64 + k0)));
    o[5] = __uint_as_float(f2tf(__ldg(W + (r1 + 8) * 64 + k0)));
    o[6] = __uint_as_float(f2tf(__ldg(W + r1 * 64 + k0 + 4)));
    o[7] = __uint_as_float(f2tf(__ldg(W + (r1 + 8) * 64 + k0 + 4)));
}

// ---------------------------------------------------------------------------
// Pass 1 / Pass 3: 2D FWHT of 128x128 image, output TRANSPOSED, scaled.
// (Exact R5-proven structure: 256 threads, 64 floats/thread, XOR swizzle.)
// ---------------------------------------------------------------------------
__global__ void __launch_bounds__(256, 2)
fwht2d_kernel(const float* __restrict__ in, float* __restrict__ out,
              float scale, int do_round)
{
    extern __shared__ float s[];
    const int img = blockIdx.x;
    const int tid = threadIdx.x;
    const float* gin  = in  + (size_t)img * NPIX;
    float*       gout = out + (size_t)img * NPIX;

    #pragma unroll
    for (int k = 0; k < 16; k++) {
        int gi = k * 256 + tid;
        int r  = gi >> 5;
        int c4 = gi & 31;
        float4 v4 = __ldg((const float4*)gin + gi);
        *(float4*)&s[sidx4(r, c4)] = v4;
    }
    __syncthreads();

    float reg[64];

    // phase W
    {
        int r = tid >> 1, half = tid & 1;
        #pragma unroll
        for (int j4 = 0; j4 < 16; j4++) {
            float4 a = *(const float4*)&s[sidx4(r, j4)];
            float4 b = *(const float4*)&s[sidx4(r, j4 + 16)];
            if (half) {
                reg[4*j4+0] = a.x - b.x; reg[4*j4+1] = a.y - b.y;
                reg[4*j4+2] = a.z - b.z; reg[4*j4+3] = a.w - b.w;
            } else {
                reg[4*j4+0] = a.x + b.x; reg[4*j4+1] = a.y + b.y;
                reg[4*j4+2] = a.z + b.z; reg[4*j4+3] = a.w + b.w;
            }
        }
        #pragma unroll
        for (int st = 1; st < 64; st <<= 1)
            #pragma unroll
            for (int i = 0; i < 64; i++)
                if ((i & st) == 0) {
                    float a = reg[i], b = reg[i + st];
                    reg[i] = a + b;  reg[i + st] = a - b;
                }
        __syncthreads();
        #pragma unroll
        for (int j4 = 0; j4 < 16; j4++)
            *(float4*)&s[sidx4(r, half * 16 + j4)] =
                make_float4(reg[4*j4], reg[4*j4+1], reg[4*j4+2], reg[4*j4+3]);
    }
    __syncthreads();

    // phase H (writes transposed)
    {
        int w = tid & 127, hh = tid >> 7;
        #pragma unroll
        for (int j = 0; j < 64; j++) {
            float a = s[sidx(j, w)];
            float b = s[sidx(j + 64, w)];
            reg[j] = hh ? (a - b) : (a + b);
        }
        #pragma unroll
        for (int st = 1; st < 64; st <<= 1)
            #pragma unroll
            for (int i = 0; i < 64; i++)
                if ((i & st) == 0) {
                    float a = reg[i], b = reg[i + st];
                    reg[i] = a + b;  reg[i + st] = a - b;
                }
        __syncthreads();
        #pragma unroll
        for (int j4 = 0; j4 < 16; j4++)
            *(float4*)&s[sidx4(w, hh * 16 + j4)] =
                make_float4(reg[4*j4], reg[4*j4+1], reg[4*j4+2], reg[4*j4+3]);
    }
    __syncthreads();

    if (do_round) {
        #pragma unroll
        for (int k = 0; k < 16; k++) {
            int gi = k * 256 + tid;
            int r  = gi >> 5;
            int c4 = gi & 31;
            float4 t = *(const float4*)&s[sidx4(r, c4)];
            ((float4*)gout)[gi] = make_float4(
                __uint_as_float(f2tf(t.x)), __uint_as_float(f2tf(t.y)),
                __uint_as_float(f2tf(t.z)), __uint_as_float(f2tf(t.w)));
        }
    } else {
        #pragma unroll
        for (int k = 0; k < 16; k++) {
            int gi = k * 256 + tid;
            int r  = gi >> 5;
            int c4 = gi & 31;
            float4 t = *(const float4*)&s[sidx4(r, c4)];
            ((float4*)gout)[gi] = make_float4(t.x*scale, t.y*scale, t.z*scale, t.w*scale);
        }
    }
}

// ---------------------------------------------------------------------------
// Pass 2: mma.sync tf32, HALF-TILE blocks for occupancy.
// Block = (b, w, nhalf): loads only h-columns [nhalf*64, +64) of the f2 tile
// (GEMM column h needs only B column h -> clean split, no duplicate traffic,
// disjoint in-place stores). 8 warps, warp (mq, nq): rows mq*16 (+pods),
// cols nq*32 within the half. acc 32 regs -> 3 blocks/SM (24 warps).
// ---------------------------------------------------------------------------
__global__ void __launch_bounds__(256, 3)
podmix_kernel(float* __restrict__ f2, const float* __restrict__ v,
              const float* __restrict__ T)
{
    __shared__ float sm[4608 + 256];
    float*    Bs  = sm;               // [64 c][72 hl] tf32 bits (local h window)
    uint32_t* Bsu = (uint32_t*)sm;
    float*    vt  = sm + 4608;        // vs0[64] Ts0[64] vs1[64] Ts1[64]

    const int tid  = threadIdx.x;
    const int wid  = tid >> 5;
    const int lane = tid & 31;
    const int gid  = lane >> 2;   // 0..7
    const int tig  = lane & 3;    // 0..3
    const int mq   = wid & 3;     // o-quarter (16 rows x 2 pods)
    const int nq   = wid >> 2;    // 32-col quarter within the half

    const int nhalf = blockIdx.x & 1;
    const int w     = (blockIdx.x >> 1) & 127;
    const int b     = blockIdx.x >> 8;

    float* gtile = f2 + (((size_t)b * 64) * 128 + w) * 128;   // + c*NPIX + h

    // stage half f2 tile (already tf32 bits): cols [nhalf*64, +64)
    #pragma unroll
    for (int k = 0; k < 4; k++) {
        int i4  = k * 256 + tid;         // 1024 float4
        int c   = i4 >> 4;
        int hl4 = i4 & 15;
        float4 t = __ldg((const float4*)(gtile + (size_t)c * NPIX) + nhalf * 16 + hl4);
        *(float4*)&Bs[c * 72 + hl4 * 4] = t;
    }
    // v/T columns for this (w, nhalf): local hl in [0,64)
    {
        int g  = tid >> 6;        // 0..3 -> vs0,Ts0,vs1,Ts1
        int hl = tid & 63;
        int h  = nhalf * 64 + hl;
        const float* src = (g & 2) ? ((g & 1) ? T + NPIX : v + NPIX)
                                   : ((g & 1) ? T : v);
        vt[g * 64 + hl] = __ldg(src + h * 128 + w);
    }
    __syncthreads();

    float acc[8][4];
    #pragma unroll
    for (int i = 0; i < 8; i++) {
        acc[i][0] = 0.f; acc[i][1] = 0.f; acc[i][2] = 0.f; acc[i][3] = 0.f;
    }

    const float4* Aw = (const float4*)g_wtf;

    #pragma unroll
    for (int kb = 0; kb < 8; kb++) {
        int ai = (((kb * 4 + mq) * 8 + gid) * 4 + tig) * 2;
        float4 lo = __ldg(Aw + ai);
        float4 hi = __ldg(Aw + ai + 1);
        uint32_t a0 = __float_as_uint(lo.x), a1 = __float_as_uint(lo.y);
        uint32_t a2 = __float_as_uint(lo.z), a3 = __float_as_uint(lo.w);
        uint32_t a4 = __float_as_uint(hi.x), a5 = __float_as_uint(hi.y);
        uint32_t a6 = __float_as_uint(hi.z), a7 = __float_as_uint(hi.w);
        int r0 = (kb * 8 + tig) * 72 + nq * 32 + gid;
        int r1 = r0 + 4 * 72;
        #pragma unroll
        for (int nb = 0; nb < 4; nb++) {
            uint32_t b0 = Bsu[r0 + nb * 8];
            uint32_t b1 = Bsu[r1 + nb * 8];
            mma_tf32(acc[nb],     a0, a1, a2, a3, b0, b1);   // pod 0
            mma_tf32(acc[4 + nb], a4, a5, a6, a7, b0, b1);   // pod 1
        }
    }
    __syncthreads();   // all GEMM reads of Bs done

    // epilogue: combine pods in registers, add f2, write back into Bs
    {
        const float* vs0 = vt;
        const float* Ts0 = vt + 64;
        const float* vs1 = vt + 128;
        const float* Ts1 = vt + 192;
        const int o = mq * 16 + gid;
        #pragma unroll
        for (int nb = 0; nb < 4; nb++) {
            int hl = nq * 32 + nb * 8 + 2 * tig;
            float v0h = vs0[hl], v0h1 = vs0[hl+1], t0h = Ts0[hl], t0h1 = Ts0[hl+1];
            float v1h = vs1[hl], v1h1 = vs1[hl+1], t1h = Ts1[hl], t1h1 = Ts1[hl+1];
            float2 f0 = *(const float2*)&Bs[o * 72 + hl];
            float2 f1 = *(const float2*)&Bs[(o + 8) * 72 + hl];
            float2 r0 = make_float2(
                softth(v0h  * acc[nb][0], t0h)  + softth(v1h  * acc[4+nb][0], t1h)  + f0.x,
                softth(v0h1 * acc[nb][1], t0h1) + softth(v1h1 * acc[4+nb][1], t1h1) + f0.y);
            float2 r1 = make_float2(
                softth(v0h  * acc[nb][2], t0h)  + softth(v1h  * acc[4+nb][2], t1h)  + f1.x,
                softth(v0h1 * acc[nb][3], t0h1) + softth(v1h1 * acc[4+nb][3], t1h1) + f1.y);
            *(float2*)&Bs[o * 72 + hl]       = r0;
            *(float2*)&Bs[(o + 8) * 72 + hl] = r1;
        }
    }
    __syncthreads();

    // coalesced store back in place (disjoint h-half per block)
    #pragma unroll
    for (int k = 0; k < 4; k++) {
        int i4  = k * 256 + tid;
        int c   = i4 >> 4;
        int hl4 = i4 & 15;
        float4 t = *(const float4*)&Bs[c * 72 + hl4 * 4];
        *((float4*)(gtile + (size_t)c * NPIX) + nhalf * 16 + hl4) = t;
    }
}

extern "C" void kernel_launch(void* const* d_in, const int* in_sizes, int n_in,
                              void* d_out, int out_size)
{
    (void)in_sizes; (void)n_in; (void)out_size;
    const float* x = (const float*)d_in[0];
    const float* v = (const float*)d_in[1];
    const float* T = (const float*)d_in[2];
    const float* W = (const float*)d_in[3];
    float* out = (float*)d_out;

    float* scratch = nullptr;
    cudaGetSymbolAddress((void**)&scratch, g_scratch);

    const int smem1 = 128 * 128 * 4;   // 65536 B
    cudaFuncSetAttribute(fwht2d_kernel, cudaFuncAttributeMaxDynamicSharedMemorySize, smem1);

    prep_kernel<<<4, 256>>>(W);
    fwht2d_kernel<<<NIMG, 256, smem1>>>(x, scratch, 1.0f, 1);
    podmix_kernel<<<B_ * 128 * 2, 256>>>(scratch, v, T);
    fwht2d_kernel<<<NIMG, 256, smem1>>>(scratch, out, 1.0f / 16384.0f, 0);
}